// round 8
// baseline (speedup 1.0000x reference)
#include <cuda_runtime.h>

// Problem constants
#define BN    4096
#define NFEAT 1024
#define RR    64
#define KK    32
#define DD    16

// Tiling
#define BT      8       // b rows per tile
#define RG      8       // regions per block (warp = one region)
#define THREADS 256
#define GRIDX   55      // 55 x 8 groups = 440 blocks ~= 3 per SM
#define NTILES  (BN / BT)   // 512 b-tiles

#define XPITCH 1028     // smem pitch for raw x rows (bank-decorrelated gather)
#define GPITCH 136      // per-region gathered tile: 2 halves of 68 floats

#define LOG_2PI_F 1.8378770664093453f

typedef unsigned long long u64;

// Packed fp32x2 helpers (sm_103a FFMA2 — only reachable via PTX)
__device__ __forceinline__ u64 ffma2(u64 a, u64 b, u64 c) {
    u64 d;
    asm("fma.rn.f32x2 %0, %1, %2, %3;" : "=l"(d) : "l"(a), "l"(b), "l"(c));
    return d;
}
__device__ __forceinline__ u64 addf2(u64 a, u64 b) {
    u64 d;
    asm("add.rn.f32x2 %0, %1, %2;" : "=l"(d) : "l"(a), "l"(b));
    return d;
}
__device__ __forceinline__ u64 bcast2(float v) {
    u64 d;
    unsigned int r = __float_as_uint(v);
    asm("mov.b64 %0, {%1, %1};" : "=l"(d) : "r"(r));
    return d;
}
__device__ __forceinline__ void unpack2(u64 v, float& lo, float& hi) {
    unsigned int a, b;
    asm("mov.b64 {%0, %1}, %2;" : "=r"(a), "=r"(b) : "l"(v));
    lo = __uint_as_float(a);
    hi = __uint_as_float(b);
}
__device__ __forceinline__ unsigned int smem_u32(const void* p) {
    unsigned int a;
    asm("{ .reg .u64 t; cvta.to.shared.u64 t, %1; cvt.u32.u64 %0, t; }"
        : "=r"(a) : "l"(p));
    return a;
}

// Precomputed parameters (device globals: no allocation allowed)
__device__ u64   g_wpa[RR * DD * KK];  // [r][d][k] = broadcast2(1/scale)
__device__ u64   g_wpb[RR * DD * KK];  // [r][d][k] = broadcast2(-mean/scale)
__device__ float g_c [RR * KK];        // [r][k]
__device__ int   g_idx[RR * DD];       // region indices as int32

// ---------------------------------------------------------------------------
// Prep kernel: 64 blocks (one per region) x 512 threads.
// ---------------------------------------------------------------------------
__global__ void prep_kernel(const float* __restrict__ means,
                            const float* __restrict__ scales,
                            const void*  __restrict__ regions_raw) {
    const int r = blockIdx.x;
    const int t = threadIdx.x;       // 0..511
    const int k = t >> 4;
    const int d = t & 15;

    const float s   = scales[((size_t)r * KK + k) * DD + d];
    const float m   = means [((size_t)r * KK + k) * DD + d];
    const float inv = 1.0f / s;
    g_wpa[(r * DD + d) * KK + k] = bcast2(inv);
    g_wpb[(r * DD + d) * KK + k] = bcast2(-m * inv);

    float lg = logf(s);
#pragma unroll
    for (int o = 8; o >= 1; o >>= 1)
        lg += __shfl_xor_sync(0xffffffffu, lg, o);
    if (d == 0)
        g_c[r * KK + k] = -lg - 0.5f * (float)DD * LOG_2PI_F;

    if (r == 0) {
        // int64 detection: if regions is int64 (values < 1024), every odd
        // 32-bit word is zero.
        __shared__ int s_or;
        if (t == 0) s_or = 0;
        __syncthreads();
        const int* w = (const int*)regions_raw;
        int v = w[2 * t + 1];
#pragma unroll
        for (int o = 16; o >= 1; o >>= 1)
            v |= __shfl_xor_sync(0xffffffffu, v, o);
        if ((t & 31) == 0) atomicOr(&s_or, v);
        __syncthreads();
        const int is64 = (s_or == 0);
        g_idx[2 * t]     = is64 ? w[4 * t]     : w[2 * t];
        g_idx[2 * t + 1] = is64 ? w[4 * t + 2] : w[2 * t + 1];
    }
}

// ---------------------------------------------------------------------------
// Main kernel: persistent blocks, grid = (55, 8).
// Block (bx, g): 8 regions, b-tiles t = bx + j*55.
// Warp = one region. Lane = h*16 + kp:
//   h  = d-half (d in [h*8, h*8+8)) -> weight residency 8 x ulonglong2 pairs
//        (k0 and k0+1) = 32 regs, loaded once per block
//   kp = k-pair (k0 = 2*kp)
// Thread computes 8b x 2k over its 8 d; halves combined via shfl.xor(16) +
// add.f32x2 (no smem, no barrier). Double-buffered cp.async x pipeline.
// ---------------------------------------------------------------------------
__global__ __launch_bounds__(THREADS, 3)
void main_kernel(const float* __restrict__ x, float* __restrict__ out) {
    extern __shared__ float smem[];
    float* sm_x0  = smem;                        // BT*XPITCH
    float* sm_x1  = smem + BT * XPITCH;          // BT*XPITCH
    float* sm_xg  = smem + 2 * BT * XPITCH;      // RG*GPITCH
    int*   sm_idx = (int*)(sm_xg + RG * GPITCH); // RG*DD = 128

    const int tid  = threadIdx.x;
    const int r0   = blockIdx.y * RG;

    const int rl   = tid >> 5;        // region within block (warp id): 0..7
    const int lane = tid & 31;
    const int h    = lane >> 4;       // d-half: 0 or 1
    const int kp   = lane & 15;       // k-pair: k0 = kp*2
    const int r    = r0 + rl;
    const int k0   = kp * 2;

    // ---- One-time: gather indices to smem ----
    if (tid < RG * DD) sm_idx[tid] = g_idx[r0 * DD + tid];

    // ---- One-time: this thread's 8-d x 2-k weight slice (pre-packed) ----
    ulonglong2 wa[8], wb[8];   // .x = k0 broadcast, .y = k0+1 broadcast
    {
        const u64* wap = g_wpa + ((size_t)r * DD + h * 8) * KK + k0;
        const u64* wbp = g_wpb + ((size_t)r * DD + h * 8) * KK + k0;
#pragma unroll
        for (int dd = 0; dd < 8; dd++) {
            wa[dd] = *(const ulonglong2*)(wap + dd * KK);
            wb[dd] = *(const ulonglong2*)(wbp + dd * KK);
        }
    }
    const float2 c2 = *(const float2*)&g_c[r * KK + k0];

    const unsigned int s_x0 = smem_u32(sm_x0);
    const unsigned int s_x1 = smem_u32(sm_x1);

    // ---- Prologue: issue load of first tile into buf0 ----
    const int t0 = blockIdx.x;
    {
        const float* xrow = x + (size_t)t0 * BT * NFEAT;
#pragma unroll
        for (int i = tid; i < BT * (NFEAT / 4); i += THREADS) {
            const int row = i >> 8;
            const int c   = i & 255;
            const unsigned int dst = s_x0 + (unsigned)(row * XPITCH + c * 4) * 4u;
            asm volatile("cp.async.cg.shared.global [%0], [%1], 16;"
                         :: "r"(dst), "l"(xrow + (size_t)row * NFEAT + c * 4));
        }
        asm volatile("cp.async.commit_group;" ::: "memory");
    }

    // ---- Pipelined tile loop ----
    for (int j = 0, t = t0; t < NTILES; j++, t += GRIDX) {
        const int tn = t + GRIDX;
        const float* sm_cur      = (j & 1) ? sm_x1 : sm_x0;
        const unsigned int s_nxt = (j & 1) ? s_x0 : s_x1;

        if (tn < NTILES) {
            const float* xrow = x + (size_t)tn * BT * NFEAT;
#pragma unroll
            for (int i = tid; i < BT * (NFEAT / 4); i += THREADS) {
                const int row = i >> 8;
                const int c   = i & 255;
                const unsigned int dst = s_nxt + (unsigned)(row * XPITCH + c * 4) * 4u;
                asm volatile("cp.async.cg.shared.global [%0], [%1], 16;"
                             :: "r"(dst), "l"(xrow + (size_t)row * NFEAT + c * 4));
            }
            asm volatile("cp.async.commit_group;" ::: "memory");
            asm volatile("cp.async.wait_group 1;" ::: "memory");  // tile t done
        } else {
            asm volatile("cp.async.wait_group 0;" ::: "memory");
        }
        __syncthreads();

        // ---- Gather tile into sm_xg[rg][off(d) + b], off(d)=d*8+(d>=8)*4 ----
        // (+4 mid-pad puts the two d-halves in different banks)
#pragma unroll
        for (int jj = 0; jj < 4; jj++) {
            const int e  = tid + jj * THREADS;
            const int b  = e & (BT - 1);
            const int d  = (e >> 3) & (DD - 1);
            const int rg = e >> 7;
            const int col = sm_idx[rg * DD + d];
            sm_xg[rg * GPITCH + d * BT + (d >> 3) * 4 + b] =
                sm_cur[b * XPITCH + col];
        }
        __syncthreads();

        // ---- Compute: 8 d per thread; per d: 2 LDS.128 + 16 FFMA2 ----
        const float* xp = sm_xg + rl * GPITCH + h * 68;

        u64 acc0[4], acc1[4];
#pragma unroll
        for (int p = 0; p < 4; p++) { acc0[p] = 0ull; acc1[p] = 0ull; }

#pragma unroll
        for (int dd = 0; dd < 8; dd++) {
            const ulonglong2 xA = *(const ulonglong2*)(xp + dd * BT);
            const ulonglong2 xB = *(const ulonglong2*)(xp + dd * BT + 4);
            const u64 xv[4] = {xA.x, xA.y, xB.x, xB.y};
            const u64 aa0 = wa[dd].x, aa1 = wa[dd].y;
            const u64 bb0 = wb[dd].x, bb1 = wb[dd].y;
#pragma unroll
            for (int p = 0; p < 4; p++) {
                const u64 z0 = ffma2(xv[p], aa0, bb0);
                acc0[p] = ffma2(z0, z0, acc0[p]);
                const u64 z1 = ffma2(xv[p], aa1, bb1);
                acc1[p] = ffma2(z1, z1, acc1[p]);
            }
        }

        // ---- Combine d-halves across the warp ----
#pragma unroll
        for (int p = 0; p < 4; p++) {
            acc0[p] = addf2(acc0[p], __shfl_xor_sync(0xffffffffu, acc0[p], 16));
            acc1[p] = addf2(acc1[p], __shfl_xor_sync(0xffffffffu, acc1[p], 16));
        }

        // ---- Epilogue: split b-range across halves (h=0: b0..3, h=1: b4..7)
        const int b0 = t * BT;
        const u64 nh  = bcast2(-0.5f);
        const u64 cc0 = bcast2(c2.x);
        const u64 cc1 = bcast2(c2.y);
#pragma unroll
        for (int pp = 0; pp < 2; pp++) {
            const int p = h * 2 + pp;
            const u64 o0 = ffma2(acc0[p], nh, cc0);
            const u64 o1 = ffma2(acc1[p], nh, cc1);
            float o0lo, o0hi, o1lo, o1hi;
            unpack2(o0, o0lo, o0hi);
            unpack2(o1, o1lo, o1hi);
            *(float2*)&out[((size_t)(b0 + 2 * p)     * RR + r) * KK + k0] =
                make_float2(o0lo, o1lo);
            *(float2*)&out[((size_t)(b0 + 2 * p + 1) * RR + r) * KK + k0] =
                make_float2(o0hi, o1hi);
        }
    }
}

// ---------------------------------------------------------------------------
#define SMEM_BYTES ((2 * BT * XPITCH + RG * GPITCH) * 4 + RG * DD * 4)

extern "C" void kernel_launch(void* const* d_in, const int* in_sizes, int n_in,
                              void* d_out, int out_size) {
    const float* x       = (const float*)d_in[0];
    const void*  regions = d_in[1];                // int64 or int32, detected
    const float* means   = (const float*)d_in[2];
    const float* scales  = (const float*)d_in[3];
    float*       out     = (float*)d_out;

    cudaFuncSetAttribute(main_kernel,
                         cudaFuncAttributeMaxDynamicSharedMemorySize,
                         SMEM_BYTES);

    prep_kernel<<<RR, 512>>>(means, scales, regions);

    dim3 grid(GRIDX, RR / RG);
    main_kernel<<<grid, THREADS, SMEM_BYTES>>>(x, out);
}

// round 9
// speedup vs baseline: 2.0359x; 2.0359x over previous
#include <cuda_runtime.h>

// Problem constants
#define BN    4096
#define NFEAT 1024
#define RR    64
#define KK    32
#define DD    16
#define NRD   (RR * DD)        // 1024 (r,d) pairs

#define LOG_2PI_F 1.8378770664093453f

// Main-kernel tiling
#define BT      8              // b rows per warp-tile
#define NTILES  (BN / BT)      // 512
#define MGX     7              // main grid.x; warp-stride = MGX*8 = 56
#define WSTRIDE (MGX * 8)
#define DEPTH   4              // per-warp cp.async ring depth

// Gather-kernel tiling
#define GB      64             // b rows per gather block
#define GC      128            // columns per gather block
#define NBIN    (NFEAT / GC)   // 8 column bins

typedef unsigned long long u64;

// Packed fp32x2 helpers (sm_103a FFMA2 — only reachable via PTX)
__device__ __forceinline__ u64 ffma2(u64 a, u64 b, u64 c) {
    u64 d;
    asm("fma.rn.f32x2 %0, %1, %2, %3;" : "=l"(d) : "l"(a), "l"(b), "l"(c));
    return d;
}
__device__ __forceinline__ u64 bcast2(float v) {
    u64 d;
    unsigned int r = __float_as_uint(v);
    asm("mov.b64 %0, {%1, %1};" : "=l"(d) : "r"(r));
    return d;
}
__device__ __forceinline__ void unpack2(u64 v, float& lo, float& hi) {
    unsigned int a, b;
    asm("mov.b64 {%0, %1}, %2;" : "=r"(a), "=r"(b) : "l"(v));
    lo = __uint_as_float(a);
    hi = __uint_as_float(b);
}
__device__ __forceinline__ unsigned int smem_u32(const void* p) {
    unsigned int a;
    asm("{ .reg .u64 t; cvta.to.shared.u64 t, %1; cvt.u32.u64 %0, t; }"
        : "=r"(a) : "l"(p));
    return a;
}

// Device globals (no runtime allocation allowed)
__device__ float g_wa[RR * KK * DD];   // [r][k][d] = 1/scale
__device__ float g_wb[RR * KK * DD];   // [r][k][d] = -mean/scale
__device__ float g_c [RR * KK];        // [r][k]
__device__ int   g_idx[NRD];           // [r][d] column index
__device__ int   g_srt_rd [NRD];       // entries sorted by column bin
__device__ int   g_srt_col[NRD];
__device__ int   g_bin_start[NBIN + 1];
__device__ float g_xg[(size_t)NRD * BN];  // [rd][b]  pre-gathered x (16.8 MB)

// ---------------------------------------------------------------------------
// Prep: 64 blocks (one per region) x 512 threads.
// Weights ([r][k][d] layout), log-det constant, index extraction (int64/int32
// auto-detect), and an 8-bin counting sort of (rd, col) by column bin.
// ---------------------------------------------------------------------------
__global__ void prep_kernel(const float* __restrict__ means,
                            const float* __restrict__ scales,
                            const void*  __restrict__ regions_raw) {
    const int r = blockIdx.x;
    const int t = threadIdx.x;       // 0..511
    const int k = t >> 4;
    const int d = t & 15;

    const size_t wi = (size_t)r * 512 + t;   // == (r*KK + k)*DD + d
    const float s   = scales[wi];
    const float m   = means [wi];
    const float inv = 1.0f / s;
    g_wa[wi] = inv;
    g_wb[wi] = -m * inv;

    float lg = logf(s);
#pragma unroll
    for (int o = 8; o >= 1; o >>= 1)
        lg += __shfl_xor_sync(0xffffffffu, lg, o);
    if (d == 0)
        g_c[r * KK + k] = -lg - 0.5f * (float)DD * LOG_2PI_F;

    if (r == 0) {
        // int64 detection: values < 1024, so if int64 every odd word is 0.
        __shared__ int s_or;
        __shared__ int s_cnt[NBIN];
        __shared__ int s_pos[NBIN];
        if (t == 0) s_or = 0;
        if (t < NBIN) s_cnt[t] = 0;
        __syncthreads();
        const int* w = (const int*)regions_raw;
        int v = w[2 * t + 1];
#pragma unroll
        for (int o = 16; o >= 1; o >>= 1)
            v |= __shfl_xor_sync(0xffffffffu, v, o);
        if ((t & 31) == 0) atomicOr(&s_or, v);
        __syncthreads();
        const int is64 = (s_or == 0);
        const int c0 = is64 ? w[4 * t]     : w[2 * t];
        const int c1 = is64 ? w[4 * t + 2] : w[2 * t + 1];
        g_idx[2 * t]     = c0;
        g_idx[2 * t + 1] = c1;

        // counting sort by column bin (col >> 7)
        atomicAdd(&s_cnt[c0 >> 7], 1);
        atomicAdd(&s_cnt[c1 >> 7], 1);
        __syncthreads();
        if (t == 0) {
            int acc = 0;
            for (int bb = 0; bb < NBIN; bb++) {
                g_bin_start[bb] = acc;
                s_pos[bb] = acc;
                acc += s_cnt[bb];
            }
            g_bin_start[NBIN] = acc;   // == 1024
        }
        __syncthreads();
        int p0 = atomicAdd(&s_pos[c0 >> 7], 1);
        g_srt_rd[p0] = 2 * t;      g_srt_col[p0] = c0;
        int p1 = atomicAdd(&s_pos[c1 >> 7], 1);
        g_srt_rd[p1] = 2 * t + 1;  g_srt_col[p1] = c1;
    }
}

// ---------------------------------------------------------------------------
// Gather: build g_xg[rd][b]. Grid (BN/GB=64, NBIN=8), 256 threads.
// Block: load x[b0:b0+64][c0:c0+128] into an XOR-swizzled smem tile
// (conflict-free column reads), then for each sorted entry in this column
// bin write 64 consecutive b's (256B coalesced) to g_xg.
// ---------------------------------------------------------------------------
__global__ __launch_bounds__(256)
void gather_kernel(const float* __restrict__ x) {
    __shared__ float sx[GB * GC];    // 32 KB, float-XOR swizzled

    const int t  = threadIdx.x;
    const int b0 = blockIdx.x * GB;
    const int cc = blockIdx.y;
    const int c0 = cc * GC;

    // Load & swizzle: sx[row*GC + (c ^ (row & 31))] = x[b0+row][c0+c]
#pragma unroll
    for (int i = 0; i < GB * GC / 256; i++) {   // 32 iters
        const int g   = i * 256 + t;
        const int row = g >> 7;                 // / GC
        const int c   = g & (GC - 1);
        sx[row * GC + (c ^ (row & 31))] =
            x[(size_t)(b0 + row) * NFEAT + c0 + c];
    }
    __syncthreads();

    // Entries for this column bin: 4 entries x 64 b's per iteration
    const int e0  = g_bin_start[cc];
    const int e1  = g_bin_start[cc + 1];
    const int sub = t >> 6;       // 0..3
    const int b   = t & 63;
    for (int e = e0 + sub; e < e1; e += 4) {
        const int rd  = g_srt_rd[e];
        const int col = g_srt_col[e] - c0;
        g_xg[(size_t)rd * BN + b0 + b] = sx[b * GC + (col ^ (b & 31))];
    }
}

// ---------------------------------------------------------------------------
// Main: grid (MGX=7, RR=64), 256 threads = 8 independent warps.
// Warp = region blockIdx.y, warp-slot wg = blockIdx.x*8 + w; b-tiles
// t = wg + j*56. Private 4-deep cp.async ring per warp, NO block barriers.
// Lane k computes 8b x 1k; per d: 2 broadcast LDS.128 + 2 movs + 8 FFMA2.
// ---------------------------------------------------------------------------
__global__ __launch_bounds__(256, 3)
void main_kernel(float* __restrict__ out) {
    __shared__ float ring[8][DEPTH][DD * BT];   // 8 x 4 x 128 floats = 16 KB

    const int tid  = threadIdx.x;
    const int w    = tid >> 5;
    const int lane = tid & 31;
    const int r    = blockIdx.y;
    const int k    = lane;

    // ---- Weights: 32 scalar regs, loaded once (contiguous [r][k][d]) ----
    float wa[DD], wb[DD];
    {
        const float4* wap = (const float4*)&g_wa[((size_t)r * KK + k) * DD];
        const float4* wbp = (const float4*)&g_wb[((size_t)r * KK + k) * DD];
#pragma unroll
        for (int j = 0; j < DD / 4; j++) {
            ((float4*)wa)[j] = wap[j];
            ((float4*)wb)[j] = wbp[j];
        }
    }
    const u64 cc = bcast2(g_c[r * KK + k]);
    const u64 nh = bcast2(-0.5f);

    const int wg = blockIdx.x * 8 + w;            // 0..55
    const float* xgr = g_xg + (size_t)r * DD * BN;

    // cp.async lane roles: lane -> (d = lane>>1, half = lane&1), 16B each
    const int ld_d = lane >> 1;
    const int ld_h = lane & 1;
    const unsigned sbase = smem_u32(&ring[w][0][0]);
    const float* ld_src0 = xgr + (size_t)ld_d * BN + ld_h * 4;

    // ---- Prologue: fill stages 0..DEPTH-2 ----
#pragma unroll
    for (int p = 0; p < DEPTH - 1; p++) {
        const int t = wg + p * WSTRIDE;
        if (t < NTILES) {
            const unsigned dst =
                sbase + (unsigned)(p * (DD * BT) + ld_d * BT + ld_h * 4) * 4u;
            asm volatile("cp.async.cg.shared.global [%0], [%1], 16;"
                         :: "r"(dst), "l"(ld_src0 + (size_t)t * BT));
        }
        asm volatile("cp.async.commit_group;" ::: "memory");
    }

    // ---- Per-warp pipelined tile loop (no block barriers) ----
    for (int j = 0, t = wg; t < NTILES; j++, t += WSTRIDE) {
        // Complete the oldest group (tile t); 2 groups stay in flight.
        asm volatile("cp.async.wait_group 2;" ::: "memory");
        __syncwarp();

        // Refill: tile t+3*W into stage (j+3)&3 (its compute ended at j-1).
        const int tf = t + (DEPTH - 1) * WSTRIDE;
        if (tf < NTILES) {
            const unsigned dst =
                sbase + (unsigned)(((j + 3) & 3) * (DD * BT) +
                                   ld_d * BT + ld_h * 4) * 4u;
            asm volatile("cp.async.cg.shared.global [%0], [%1], 16;"
                         :: "r"(dst), "l"(ld_src0 + (size_t)tf * BT));
        }
        asm volatile("cp.async.commit_group;" ::: "memory");

        // ---- Compute tile t from stage j&3 ----
        const float* xp = &ring[w][j & 3][0];

        u64 acc[4];
#pragma unroll
        for (int p = 0; p < 4; p++) acc[p] = 0ull;

#pragma unroll
        for (int d = 0; d < DD; d++) {
            const ulonglong2 xA = *(const ulonglong2*)(xp + d * BT);      // b0..3
            const ulonglong2 xB = *(const ulonglong2*)(xp + d * BT + 4);  // b4..7
            const u64 aa = bcast2(wa[d]);
            const u64 bb = bcast2(wb[d]);
            u64 z;
            z = ffma2(xA.x, aa, bb); acc[0] = ffma2(z, z, acc[0]);
            z = ffma2(xA.y, aa, bb); acc[1] = ffma2(z, z, acc[1]);
            z = ffma2(xB.x, aa, bb); acc[2] = ffma2(z, z, acc[2]);
            z = ffma2(xB.y, aa, bb); acc[3] = ffma2(z, z, acc[3]);
        }

        // ---- Epilogue: out[b][r][k], lanes coalesce over k ----
        float* op = out + (size_t)t * BT * (RR * KK) + r * KK + k;
#pragma unroll
        for (int p = 0; p < 4; p++) {
            const u64 o = ffma2(acc[p], nh, cc);
            float lo, hi;
            unpack2(o, lo, hi);
            op[(size_t)(2 * p)     * (RR * KK)] = lo;
            op[(size_t)(2 * p + 1) * (RR * KK)] = hi;
        }
    }
}

// ---------------------------------------------------------------------------
extern "C" void kernel_launch(void* const* d_in, const int* in_sizes, int n_in,
                              void* d_out, int out_size) {
    const float* x       = (const float*)d_in[0];
    const void*  regions = d_in[1];                // int64 or int32, detected
    const float* means   = (const float*)d_in[2];
    const float* scales  = (const float*)d_in[3];
    float*       out     = (float*)d_out;

    prep_kernel<<<RR, 512>>>(means, scales, regions);
    gather_kernel<<<dim3(BN / GB, NBIN), 256>>>(x);
    main_kernel<<<dim3(MGX, RR), 256>>>(out);
}